// round 13
// baseline (speedup 1.0000x reference)
#include <cuda_runtime.h>
#include <cuda_fp16.h>
#include <cooperative_groups.h>
namespace cg = cooperative_groups;

#define THETA 0.5f
#define EPS   1e-5f

__device__ __forceinline__ unsigned fast_tanh_h2(unsigned x) {
    unsigned y;
    asm("tanh.approx.f16x2 %0, %1;" : "=r"(y) : "r"(x));
    return y;
}
__device__ __forceinline__ unsigned pack_h2(float a, float b) {
    unsigned r;
    asm("cvt.rn.f16x2.f32 %0, %1, %2;" : "=r"(r) : "f"(b), "f"(a));
    return r;
}

// Cluster of 2 CTAs owns TWO adjacent planes A=2j, B=2j+1; CTA rank r owns
// rows [128r, 128r+128) of both. 256 threads = 8 warps; warp w = 64x64 patch.
// Stage 1: stats(A) + exchange (cluster.sync + DSMEM pull).
// Stage 2: B's stats loads (DRAM) software-pipelined at distance 2 and
// interleaved with A's gate+store (L2 re-read + DRAM writes).
// Stage 3: exchange B stats, gate+store B (reverse, L2-hot, double-buffered).
// Gate tanh via tanh.approx.f16x2 (args + blend f32): halves MUFU + issue.
__global__ __launch_bounds__(256, 4) __cluster_dims__(2, 1, 1)
void pmfm_fused(const float* __restrict__ x,
                const float* __restrict__ lw,
                float* __restrict__ out) {
    cg::cluster_group cluster = cg::this_cluster();
    const unsigned rank = cluster.block_rank();

    const int cid  = blockIdx.x >> 1;     // cluster id -> planes 2*cid, 2*cid+1
    const int t    = threadIdx.x;
    const int w    = t >> 5;              // warp 0..7 = local patch
    const int lane = t & 31;
    const int prow = (int)rank * 2 + (w >> 2);
    const int pcol = w & 3;

    const size_t planeA = (size_t)(2 * cid) * 65536;
    const int colf  = pcol * 64 + (lane & 15) * 4;
    const int rbase = prow * 64 + (lane >> 4);      // start row (stride 2)
    const size_t off = (size_t)rbase * 256 + colf;

    const float4* pinA = reinterpret_cast<const float4*>(x + planeA + off);
    const float4* pinB = reinterpret_cast<const float4*>(x + planeA + 65536 + off);
    float4*       poA  = reinterpret_cast<float4*>(out + planeA + off);
    float4*       poB  = reinterpret_cast<float4*>(out + planeA + 65536 + off);

    __shared__ float2 st[8];        // per-patch stats (reused for A then B)
    __shared__ float2 sh_half;      // this CTA's half-plane total (A then B)

    // softmax(level_weights) — constant for both planes
    const float w0 = __ldg(lw + 0), w1 = __ldg(lw + 1), w2 = __ldg(lw + 2);
    const float mmx = fmaxf(w0, fmaxf(w1, w2));
    const float ew0 = __expf(w0 - mmx), ew1 = __expf(w1 - mmx), ew2 = __expf(w2 - mmx);
    const float cc = (1.f - THETA) * 0.5f / (ew0 + ew1 + ew2);
    const float cf = cc * ew0, cm = cc * ew1, cg_ = cc * ew2;
    const float basew = THETA + (1.f - THETA) * 0.5f;
    const float iN2 = 1.f / 4096.f, iN1 = 1.f / 16384.f, iN0 = 1.f / 65536.f;

#define PMFM_SUMSQ(v, S, Q)                                                  \
    S += ((v).x + (v).y) + ((v).z + (v).w);                                  \
    Q += (v).x * (v).x + (v).y * (v).y + (v).z * (v).z + (v).w * (v).w;

    // ================= Stage 1: stats over plane A =================
    float s = 0.f, q = 0.f, s2 = 0.f, q2 = 0.f;
#pragma unroll
    for (int c = 0; c < 8; ++c) {
        const float4 va = pinA[(size_t)(4 * c + 0) * 128];
        const float4 vb = pinA[(size_t)(4 * c + 1) * 128];
        const float4 vc = pinA[(size_t)(4 * c + 2) * 128];
        const float4 vd = pinA[(size_t)(4 * c + 3) * 128];
        PMFM_SUMSQ(va, s, q)  PMFM_SUMSQ(vb, s2, q2)
        PMFM_SUMSQ(vc, s, q)  PMFM_SUMSQ(vd, s2, q2)
    }
    s += s2; q += q2;
#pragma unroll
    for (int o = 16; o > 0; o >>= 1) {
        s += __shfl_xor_sync(0xffffffffu, s, o);
        q += __shfl_xor_sync(0xffffffffu, q, o);
    }
    if (lane == 0) st[w] = make_float2(s, q);
    __syncthreads();
    if (t < 8) {
        float2 v = st[t];
        float hs = v.x, hq = v.y;
#pragma unroll
        for (int o = 4; o > 0; o >>= 1) {
            hs += __shfl_xor_sync(0x000000ffu, hs, o, 8);
            hq += __shfl_xor_sync(0x000000ffu, hq, o, 8);
        }
        if (t == 0) sh_half = make_float2(hs, hq);
    }
    cluster.sync();

    // exchange A: pull peer's half-plane total
    float phs, phq;
    {
        float2 ph = make_float2(0.f, 0.f);
        if (lane == 0)
            ph = *(const float2*)cluster.map_shared_rank((void*)&sh_half, rank ^ 1u);
        phs = __shfl_sync(0xffffffffu, ph.x, 0);
        phq = __shfl_sync(0xffffffffu, ph.y, 0);
    }
    // coefficients for A
    float a2c, b2c, a1c, b1c, a0c, b0c;
    {
        const float2 f2 = st[w];
        float s1 = 0.f, q1 = 0.f;
        const int qc = pcol & ~1;
#pragma unroll
        for (int dr = 0; dr < 2; ++dr)
#pragma unroll
            for (int dc = 0; dc < 2; ++dc) {
                const float2 v = st[dr * 4 + (qc + dc)];
                s1 += v.x; q1 += v.y;
            }
        const float s0 = sh_half.x + phs, q0 = sh_half.y + phq;
        const float mu2 = f2.x * iN2; const float v2 = fmaxf(f2.y * iN2 - mu2 * mu2, 0.f);
        const float mu1 = s1  * iN1; const float v1 = fmaxf(q1  * iN1 - mu1 * mu1, 0.f);
        const float mu0 = s0  * iN0; const float v0 = fmaxf(q0  * iN0 - mu0 * mu0, 0.f);
        a2c = 0.5f * rsqrtf(v2 + EPS); b2c = -mu2 * a2c;
        a1c = 0.5f * rsqrtf(v1 + EPS); b1c = -mu1 * a1c;
        a0c = 0.5f * rsqrtf(v0 + EPS); b0c = -mu0 * a0c;
    }

    // Gate a float4: tanh via f16x2 (2 elems/MUFU op), args + blend in f32.
#define PMFM_GATE(res, vin)                                                    \
    {                                                                          \
        const float4 _v = (vin);                                               \
        const unsigned t2a = fast_tanh_h2(pack_h2(fmaf(_v.x, a2c, b2c), fmaf(_v.y, a2c, b2c))); \
        const unsigned t2b = fast_tanh_h2(pack_h2(fmaf(_v.z, a2c, b2c), fmaf(_v.w, a2c, b2c))); \
        const unsigned t1a = fast_tanh_h2(pack_h2(fmaf(_v.x, a1c, b1c), fmaf(_v.y, a1c, b1c))); \
        const unsigned t1b = fast_tanh_h2(pack_h2(fmaf(_v.z, a1c, b1c), fmaf(_v.w, a1c, b1c))); \
        const unsigned t0a = fast_tanh_h2(pack_h2(fmaf(_v.x, a0c, b0c), fmaf(_v.y, a0c, b0c))); \
        const unsigned t0b = fast_tanh_h2(pack_h2(fmaf(_v.z, a0c, b0c), fmaf(_v.w, a0c, b0c))); \
        const __half2 h2a = *(const __half2*)&t2a, h2b = *(const __half2*)&t2b; \
        const __half2 h1a = *(const __half2*)&t1a, h1b = *(const __half2*)&t1b; \
        const __half2 h0a = *(const __half2*)&t0a, h0b = *(const __half2*)&t0b; \
        (res).x = _v.x * fmaf(cf, __low2float(h2a),  fmaf(cm, __low2float(h1a),  fmaf(cg_, __low2float(h0a),  basew))); \
        (res).y = _v.y * fmaf(cf, __high2float(h2a), fmaf(cm, __high2float(h1a), fmaf(cg_, __high2float(h0a), basew))); \
        (res).z = _v.z * fmaf(cf, __low2float(h2b),  fmaf(cm, __low2float(h1b),  fmaf(cg_, __low2float(h0b),  basew))); \
        (res).w = _v.w * fmaf(cf, __high2float(h2b), fmaf(cm, __high2float(h1b), fmaf(cg_, __high2float(h0b), basew))); \
    }

    // ===== Stage 2: B stats-reads pipelined (distance 2) + A gate+store =====
    float bs = 0.f, bq = 0.f, bs2 = 0.f, bq2 = 0.f;
    float4 vb[2][2];
    vb[0][0] = pinB[(size_t)0 * 128];
    vb[0][1] = pinB[(size_t)1 * 128];
    vb[1][0] = pinB[(size_t)2 * 128];
    vb[1][1] = pinB[(size_t)3 * 128];
#pragma unroll
    for (int c = 0; c < 16; ++c) {
        const float4 b0 = vb[c & 1][0];
        const float4 b1 = vb[c & 1][1];
        if (c < 14) {   // refill this buffer slot for chunk c+2
            vb[c & 1][0] = pinB[(size_t)(2 * (c + 2) + 0) * 128];
            vb[c & 1][1] = pinB[(size_t)(2 * (c + 2) + 1) * 128];
        }
        const float4 va0 = __ldcs(&pinA[(size_t)(2 * (15 - c) + 0) * 128]);
        const float4 va1 = __ldcs(&pinA[(size_t)(2 * (15 - c) + 1) * 128]);
        PMFM_SUMSQ(b0, bs, bq)  PMFM_SUMSQ(b1, bs2, bq2)
        float4 r0, r1;
        PMFM_GATE(r0, va0);
        PMFM_GATE(r1, va1);
        __stcs(&poA[(size_t)(2 * (15 - c) + 0) * 128], r0);
        __stcs(&poA[(size_t)(2 * (15 - c) + 1) * 128], r1);
    }

    // ================= Stage 3: B stats exchange + apply =================
    bs += bs2; bq += bq2;
#pragma unroll
    for (int o = 16; o > 0; o >>= 1) {
        bs += __shfl_xor_sync(0xffffffffu, bs, o);
        bq += __shfl_xor_sync(0xffffffffu, bq, o);
    }
    __syncthreads();               // everyone done reading st[] A-values
    if (lane == 0) st[w] = make_float2(bs, bq);
    __syncthreads();
    if (t < 8) {
        float2 v = st[t];
        float hs = v.x, hq = v.y;
#pragma unroll
        for (int o = 4; o > 0; o >>= 1) {
            hs += __shfl_xor_sync(0x000000ffu, hs, o, 8);
            hq += __shfl_xor_sync(0x000000ffu, hq, o, 8);
        }
        if (t == 0) sh_half = make_float2(hs, hq);
    }
    cluster.sync();
    {
        float2 ph = make_float2(0.f, 0.f);
        if (lane == 0)
            ph = *(const float2*)cluster.map_shared_rank((void*)&sh_half, rank ^ 1u);
        phs = __shfl_sync(0xffffffffu, ph.x, 0);   // forces pull complete
        phq = __shfl_sync(0xffffffffu, ph.y, 0);
    }
    // Early arrive: done reading peer smem; matching wait at kernel end.
    asm volatile("barrier.cluster.arrive.aligned;" ::: "memory");
    {
        const float2 f2 = st[w];
        float s1 = 0.f, q1 = 0.f;
        const int qc = pcol & ~1;
#pragma unroll
        for (int dr = 0; dr < 2; ++dr)
#pragma unroll
            for (int dc = 0; dc < 2; ++dc) {
                const float2 v = st[dr * 4 + (qc + dc)];
                s1 += v.x; q1 += v.y;
            }
        const float s0 = sh_half.x + phs, q0 = sh_half.y + phq;
        const float mu2 = f2.x * iN2; const float v2 = fmaxf(f2.y * iN2 - mu2 * mu2, 0.f);
        const float mu1 = s1  * iN1; const float v1 = fmaxf(q1  * iN1 - mu1 * mu1, 0.f);
        const float mu0 = s0  * iN0; const float v0 = fmaxf(q0  * iN0 - mu0 * mu0, 0.f);
        a2c = 0.5f * rsqrtf(v2 + EPS); b2c = -mu2 * a2c;
        a1c = 0.5f * rsqrtf(v1 + EPS); b1c = -mu1 * a1c;
        a0c = 0.5f * rsqrtf(v0 + EPS); b0c = -mu0 * a0c;
    }
    // apply B: reverse-order L2-hot re-read, double-buffered
    float4 buf[2][2];
    buf[1][0] = __ldcs(&pinB[(size_t)(2 * 15 + 0) * 128]);
    buf[1][1] = __ldcs(&pinB[(size_t)(2 * 15 + 1) * 128]);
#pragma unroll
    for (int c = 15; c >= 0; --c) {
        const float4 cur0 = buf[c & 1][0];
        const float4 cur1 = buf[c & 1][1];
        if (c > 0) {
            buf[(c - 1) & 1][0] = __ldcs(&pinB[(size_t)(2 * (c - 1) + 0) * 128]);
            buf[(c - 1) & 1][1] = __ldcs(&pinB[(size_t)(2 * (c - 1) + 1) * 128]);
        }
        float4 r0, r1;
        PMFM_GATE(r0, cur0);
        PMFM_GATE(r1, cur1);
        __stcs(&poB[(size_t)(2 * c + 0) * 128], r0);
        __stcs(&poB[(size_t)(2 * c + 1) * 128], r1);
    }
#undef PMFM_GATE
#undef PMFM_SUMSQ

    // No CTA exits while its peer might still read sh_half.
    asm volatile("barrier.cluster.wait.aligned;" ::: "memory");
}

extern "C" void kernel_launch(void* const* d_in, const int* in_sizes, int n_in,
                              void* d_out, int out_size) {
    const float* x;
    const float* lw;
    long nx;
    if (in_sizes[0] >= in_sizes[1]) {
        x = (const float*)d_in[0]; lw = (const float*)d_in[1]; nx = in_sizes[0];
    } else {
        x = (const float*)d_in[1]; lw = (const float*)d_in[0]; nx = in_sizes[1];
    }
    const int nplanes = (int)(nx / 65536);   // B*C = 512 planes of 256x256
    pmfm_fused<<<nplanes, 256>>>(x, lw, (float*)d_out);   // 2 planes / cluster
}